// round 13
// baseline (speedup 1.0000x reference)
#include <cuda_runtime.h>
#include <cuda_fp16.h>
#include <math.h>
#include <stdint.h>

// ---------------- problem constants ----------------
#define Bz    64
#define Hh    56
#define Ww    56
#define Cc    192
#define NHh   6
#define WS    7
#define SS    3
#define Nn    49
#define HD    32
#define NW    64
#define Ltok  3136
#define Mrow  200704      // B*L == 128*1568
#define MLPH  768
#define QKVN  576

// ---------------- scratch globals ----------------
__device__ __align__(16) __half g_yw[(size_t)Mrow * Cc];
__device__ __align__(16) __half g_q [(size_t)Mrow * Cc];
__device__ __align__(16) __half g_k [(size_t)Mrow * Cc];
__device__ __align__(16) __half g_v [(size_t)Mrow * Cc];
__device__ __align__(16) __half g_o [(size_t)Mrow * Cc];
__device__ __align__(16) __half g_po[(size_t)Mrow * Cc];   // proj_out+bias, SPATIAL
__device__ __align__(16) __half g_z [(size_t)Mrow * Cc];   // LN2 out, SPATIAL

// fp16 weights
__device__ __align__(16) __half g_qkvw[QKVN * Cc];
__device__ __align__(16) __half g_projw[Cc * Cc];
__device__ __align__(16) __half g_fc1w[MLPH * Cc];
__device__ __align__(16) __half g_fc2w[Cc * MLPH];

// ---------------- PTX helpers ----------------
__device__ __forceinline__ uint32_t smem_u32(const void* p) {
    uint32_t a;
    asm("{ .reg .u64 t; cvta.to.shared.u64 t, %1; cvt.u32.u64 %0, t; }"
        : "=r"(a) : "l"(p));
    return a;
}
__device__ __forceinline__ void cp16(uint32_t dst, const void* src) {
    asm volatile("cp.async.cg.shared.global [%0], [%1], 16;"
                 :: "r"(dst), "l"(src));
}
#define CP_COMMIT() asm volatile("cp.async.commit_group;" ::: "memory")
#define CP_WAIT1()  asm volatile("cp.async.wait_group 1;" ::: "memory")
#define CP_WAIT0()  asm volatile("cp.async.wait_group 0;" ::: "memory")

__device__ __forceinline__ void ldm_x4(uint32_t* r, uint32_t a) {
    asm volatile("ldmatrix.sync.aligned.m8n8.x4.shared.b16 {%0,%1,%2,%3}, [%4];"
        : "=r"(r[0]), "=r"(r[1]), "=r"(r[2]), "=r"(r[3]) : "r"(a));
}
__device__ __forceinline__ void ldm_x4t(uint32_t* r, uint32_t a) {
    asm volatile("ldmatrix.sync.aligned.m8n8.x4.trans.shared.b16 {%0,%1,%2,%3}, [%4];"
        : "=r"(r[0]), "=r"(r[1]), "=r"(r[2]), "=r"(r[3]) : "r"(a));
}
__device__ __forceinline__ void mma16816(float* d, const uint32_t* a,
                                         uint32_t b0, uint32_t b1) {
    asm volatile(
        "mma.sync.aligned.m16n8k16.row.col.f32.f16.f16.f32 "
        "{%0,%1,%2,%3}, {%4,%5,%6,%7}, {%8,%9}, {%0,%1,%2,%3};"
        : "+f"(d[0]), "+f"(d[1]), "+f"(d[2]), "+f"(d[3])
        : "r"(a[0]), "r"(a[1]), "r"(a[2]), "r"(a[3]), "r"(b0), "r"(b1));
}
__device__ __forceinline__ uint32_t pack2h(float v0, float v1) {
    __half2 h = __floats2half2_rn(v0, v1);
    return *(uint32_t*)&h;
}

// ---------------- GEMM geometry ----------------
#define GB_BYTES (192 * 128)
#define GA128    (128 * 128)
#define GSTG128  (GA128 + GB_BYTES)          // 40960
#define SMEM_G128 (3 * GSTG128)              // 122880
#define ASTR 80                               // attention smem row stride

// generic 3-stage pipelined mainloop (proj / mlp)
__device__ __forceinline__ void gemm_mma512(
    const __half* __restrict__ a, const __half* __restrict__ b,
    int K, int n0, int m0, float (&acc)[12][4])
{
    extern __shared__ char sm[];
    const uint32_t sb = smem_u32(sm);
    const int tid  = threadIdx.x;
    const int wid  = tid >> 5, lane = tid & 31;
    const int wm   = wid >> 2, wn = wid & 3;
    const int NCH  = K >> 6;

    #pragma unroll
    for (int i = 0; i < 12; i++)
        #pragma unroll
        for (int j = 0; j < 4; j++) acc[i][j] = 0.f;

    auto load_stage = [&](int stg, int c) {
        const __half* A = a + (size_t)m0 * K + c * 64;
        const __half* B = b + (size_t)n0 * K + c * 64;
        const uint32_t Ab = sb + (uint32_t)stg * GSTG128;
        const uint32_t Bb = Ab + GA128;
        #pragma unroll
        for (int i = 0; i < 2; i++) {
            const int idx = tid + i * 512;
            const int r = idx >> 3, p = idx & 7;
            cp16(Ab + r * 128 + ((p ^ (r & 7)) << 4), A + (size_t)r * K + p * 8);
        }
        #pragma unroll
        for (int i = 0; i < 3; i++) {
            const int idx = tid + i * 512;
            const int r = idx >> 3, p = idx & 7;
            cp16(Bb + r * 128 + ((p ^ (r & 7)) << 4), B + (size_t)r * K + p * 8);
        }
    };

    load_stage(0, 0); CP_COMMIT();
    load_stage(1, 1); CP_COMMIT();

    const int lrow  = lane & 15;
    const int chalf = lane >> 4;

    for (int c = 0; c < NCH; c++) {
        if (c < NCH - 1) { CP_WAIT1(); } else { CP_WAIT0(); }
        __syncthreads();
        const uint32_t Ab = sb + (uint32_t)(c % 3) * GSTG128;
        const uint32_t Bb = Ab + GA128;
        #pragma unroll
        for (int ks = 0; ks < 4; ks++) {
            const int col = ks * 2 + chalf;
            uint32_t rA[2][4], rB[3][4];
            #pragma unroll
            for (int mi = 0; mi < 2; mi++) {
                const int row = wm * 32 + mi * 16 + lrow;
                ldm_x4(rA[mi], Ab + row * 128 + ((col ^ (row & 7)) << 4));
            }
            #pragma unroll
            for (int ni = 0; ni < 3; ni++) {
                const int row = wn * 48 + ni * 16 + lrow;
                ldm_x4(rB[ni], Bb + row * 128 + ((col ^ (row & 7)) << 4));
            }
            #pragma unroll
            for (int mi = 0; mi < 2; mi++)
                #pragma unroll
                for (int nj = 0; nj < 6; nj++)
                    mma16816(acc[mi * 6 + nj], rA[mi],
                             rB[nj >> 1][nj & 1], rB[nj >> 1][(nj & 1) + 2]);
        }
        if (c + 2 < NCH) { load_stage((c + 2) % 3, c + 2); CP_COMMIT(); }
    }
    __syncthreads();   // smem buffers free
}

#define EPI_PROLOGUE()                                          \
    extern __shared__ char sm[];                                \
    const int tid = threadIdx.x;                                \
    const int wid = tid >> 5, lane = tid & 31;                  \
    const int wm = wid >> 2, wn = wid & 3;                      \
    const int g = lane >> 2, tg = lane & 3;

// ---------------- QKV GEMM: persistent-A, loops 3 parts -------------------
// smem: A chunks [0,49152) = 3 x 16KB; B stages [49152,122880) = 3 x 24KB.
#define QB_OFF 49152
#define QB_STG 24576

__global__ __launch_bounds__(512) void gemm_qkv_kernel(const float* __restrict__ qkv_b)
{
    EPI_PROLOGUE();
    const uint32_t sb = smem_u32(sm);
    const int m0 = blockIdx.x * 128;
    const int lrow  = lane & 15;
    const int chalf = lane >> 4;

    // load A tile once: 128 rows x 192 cols -> 3 swizzled 64-col chunks
    #pragma unroll
    for (int i = 0; i < 6; i++) {
        const int idx = tid + i * 512;       // 3072 x 16B
        const int r = idx / 24, u = idx - r * 24;
        const int j = u >> 3, p = u & 7;
        cp16(sb + j * 16384 + r * 128 + ((p ^ (r & 7)) << 4),
             g_yw + (size_t)(m0 + r) * Cc + u * 8);
    }
    CP_COMMIT();

    auto load_B = [&](int stg, int part, int c) {
        const __half* B = g_qkvw + (size_t)part * 192 * Cc + c * 64;
        const uint32_t Bb = sb + QB_OFF + (uint32_t)stg * QB_STG;
        #pragma unroll
        for (int i = 0; i < 3; i++) {
            const int idx = tid + i * 512;   // 1536 x 16B
            const int r = idx >> 3, p = idx & 7;
            cp16(Bb + r * 128 + ((p ^ (r & 7)) << 4), B + (size_t)r * Cc + p * 8);
        }
    };

    for (int part = 0; part < 3; part++) {
        load_B(0, part, 0); CP_COMMIT();
        load_B(1, part, 1); CP_COMMIT();

        float acc[12][4];
        #pragma unroll
        for (int i = 0; i < 12; i++)
            #pragma unroll
            for (int j = 0; j < 4; j++) acc[i][j] = 0.f;

        #pragma unroll
        for (int c = 0; c < 3; c++) {
            if (c < 2) { CP_WAIT1(); } else { CP_WAIT0(); }
            __syncthreads();
            const uint32_t Ab = sb + (uint32_t)c * 16384;
            const uint32_t Bb = sb + QB_OFF + (uint32_t)c * QB_STG;
            #pragma unroll
            for (int ks = 0; ks < 4; ks++) {
                const int col = ks * 2 + chalf;
                uint32_t rA[2][4], rB[3][4];
                #pragma unroll
                for (int mi = 0; mi < 2; mi++) {
                    const int row = wm * 32 + mi * 16 + lrow;
                    ldm_x4(rA[mi], Ab + row * 128 + ((col ^ (row & 7)) << 4));
                }
                #pragma unroll
                for (int ni = 0; ni < 3; ni++) {
                    const int row = wn * 48 + ni * 16 + lrow;
                    ldm_x4(rB[ni], Bb + row * 128 + ((col ^ (row & 7)) << 4));
                }
                #pragma unroll
                for (int mi = 0; mi < 2; mi++)
                    #pragma unroll
                    for (int nj = 0; nj < 6; nj++)
                        mma16816(acc[mi * 6 + nj], rA[mi],
                                 rB[nj >> 1][nj & 1], rB[nj >> 1][(nj & 1) + 2]);
            }
            if (c == 0) { load_B(2, part, 2); CP_COMMIT(); }
        }
        __syncthreads();   // B stages free for staging

        // epilogue: stage fp16 into B region, coalesced scatter
        __half* dst = (part == 0) ? g_q : ((part == 1) ? g_k : g_v);
        const float sc = (part == 0) ? 0.17677669529663687f : 1.0f;
        __half* sh = (__half*)(sm + QB_OFF);    // [128][192]
        #pragma unroll
        for (int t = 0; t < 12; t++) {
            const int mi = t / 6, nj = t % 6;
            const int c = wn * 48 + nj * 8 + tg * 2;
            const float b0 = qkv_b[part * 192 + c];
            const float b1 = qkv_b[part * 192 + c + 1];
            #pragma unroll
            for (int h = 0; h < 2; h++) {
                const int r = wm * 32 + mi * 16 + g + h * 8;
                *(uint32_t*)(sh + r * 192 + c) =
                    pack2h((acc[t][h * 2 + 0] + b0) * sc,
                           (acc[t][h * 2 + 1] + b1) * sc);
            }
        }
        __syncthreads();
        #pragma unroll
        for (int i = 0; i < 6; i++) {
            const int idx = tid + i * 512;    // 3072 = 128 rows x 24 segs
            const int r = idx / 24, s = idx - r * 24;
            const int head = s >> 2, d = (s & 3) * 8;
            const int m = m0 + r;
            const int win = m / Nn, n = m - win * Nn;
            const uint4 v = *(const uint4*)(sh + r * 192 + s * 8);
            *(uint4*)(dst + ((size_t)(win * NHh + head) * Nn + n) * HD + d) = v;
        }
        __syncthreads();   // staging free before next part's B loads
    }
}

// ---------------- proj GEMM + FUSED LN2 ----------------
__global__ __launch_bounds__(512) void gemm_proj_kernel(
    const float* __restrict__ proj_b, const float* __restrict__ x_shortcut,
    const float* __restrict__ norm2_g, const float* __restrict__ norm2_b)
{
    float acc[12][4];
    const int m0 = blockIdx.y * 128;
    gemm_mma512(g_o, g_projw, Cc, 0, m0, acc);
    EPI_PROLOGUE();
    float* sh = (float*)sm;    // [128][192]
    #pragma unroll
    for (int t = 0; t < 12; t++) {
        const int mi = t / 6, nj = t % 6;
        const int cn = wn * 48 + nj * 8 + tg * 2;
        const float b0 = proj_b[cn], b1 = proj_b[cn + 1];
        #pragma unroll
        for (int h = 0; h < 2; h++) {
            const int r = wm * 32 + mi * 16 + g + h * 8;
            *(float2*)(sh + r * 192 + cn) =
                make_float2(acc[t][h * 2 + 0] + b0, acc[t][h * 2 + 1] + b1);
        }
    }
    __syncthreads();
    float gg[6], bb[6];
    #pragma unroll
    for (int i = 0; i < 6; i++) {
        gg[i] = norm2_g[lane * 6 + i];
        bb[i] = norm2_b[lane * 6 + i];
    }
    for (int r = wid; r < 128; r += 16) {
        const int m = m0 + r;
        const int win = m / Nn, n = m - win * Nn;
        const int bi = win >> 6, w_ = win & 63;
        const int wr = w_ >> 3, wc = w_ & 7;
        const int pr = n / WS, pc = n - pr * WS;
        int ho = wr * WS + pr + SS; if (ho >= Hh) ho -= Hh;
        int wo = wc * WS + pc + SS; if (wo >= Ww) wo -= Ww;
        const size_t gidx = ((size_t)bi * Ltok + ho * Ww + wo) * Cc;

        float v[6], po[6];
        const float* xr = x_shortcut + gidx + lane * 6;
        const float* sr = sh + r * 192 + lane * 6;
        float2 t0 = *(const float2*)(xr);
        float2 t1 = *(const float2*)(xr + 2);
        float2 t2 = *(const float2*)(xr + 4);
        po[0] = sr[0]; po[1] = sr[1]; po[2] = sr[2];
        po[3] = sr[3]; po[4] = sr[4]; po[5] = sr[5];
        v[0] = t0.x + po[0]; v[1] = t0.y + po[1];
        v[2] = t1.x + po[2]; v[3] = t1.y + po[3];
        v[4] = t2.x + po[4]; v[5] = t2.y + po[5];

        float s = 0.f, ss = 0.f;
        #pragma unroll
        for (int i = 0; i < 6; i++) { s += v[i]; ss += v[i] * v[i]; }
        #pragma unroll
        for (int off = 16; off > 0; off >>= 1) {
            s  += __shfl_xor_sync(0xffffffffu, s,  off);
            ss += __shfl_xor_sync(0xffffffffu, ss, off);
        }
        const float mean = s * (1.f / Cc);
        const float rstd = rsqrtf(ss * (1.f / Cc) - mean * mean + 1e-5f);

        __half* pr_ = g_po + gidx + lane * 6;
        *(uint32_t*)(pr_)     = pack2h(po[0], po[1]);
        *(uint32_t*)(pr_ + 2) = pack2h(po[2], po[3]);
        *(uint32_t*)(pr_ + 4) = pack2h(po[4], po[5]);

        __half* zr = g_z + gidx + lane * 6;
        *(uint32_t*)(zr)     = pack2h((v[0]-mean)*rstd*gg[0]+bb[0], (v[1]-mean)*rstd*gg[1]+bb[1]);
        *(uint32_t*)(zr + 2) = pack2h((v[2]-mean)*rstd*gg[2]+bb[2], (v[3]-mean)*rstd*gg[3]+bb[3]);
        *(uint32_t*)(zr + 4) = pack2h((v[4]-mean)*rstd*gg[4]+bb[4], (v[5]-mean)*rstd*gg[5]+bb[5]);
    }
}

// ---------------- FUSED MLP (512 thr, 128-row tiles) ----------------
__global__ __launch_bounds__(512) void gemm_mlp_kernel(
    const float* __restrict__ fc1_b, const float* __restrict__ bn_g,
    const float* __restrict__ bn_b,  const float* __restrict__ fc2_b,
    const float* __restrict__ x_shortcut, float* __restrict__ out)
{
    EPI_PROLOGUE();
    const int m0 = blockIdx.y * 128;
    const uint32_t sb = smem_u32(sm);
    const int lrow  = lane & 15;
    const int chalf = lane >> 4;
    const float bnscale = 0.9999950000374997f;  // 1/sqrt(1+1e-5)

    float acc2[12][4];
    #pragma unroll
    for (int i = 0; i < 12; i++)
        #pragma unroll
        for (int j = 0; j < 4; j++) acc2[i][j] = 0.f;

    for (int nt = 0; nt < 4; nt++) {
        float acc1[12][4];
        gemm_mma512(g_z, g_fc1w, Cc, nt * 192, m0, acc1);

        // BN + GELU -> fp16 into A-buffers (swizzled)
        #pragma unroll
        for (int t = 0; t < 12; t++) {
            const int mi = t / 6, nj = t % 6;
            const int c = wn * 48 + nj * 8 + tg * 2;
            const int cn = nt * 192 + c;
            const float fb0 = fc1_b[cn],  fb1 = fc1_b[cn + 1];
            const float sg0 = bnscale * bn_g[cn], sg1 = bnscale * bn_g[cn + 1];
            const float bb0 = bn_b[cn], bb1 = bn_b[cn + 1];
            const int j = c >> 6, u = (c & 63) >> 3;
            #pragma unroll
            for (int h = 0; h < 2; h++) {
                const int r = wm * 32 + mi * 16 + g + h * 8;
                float v0 = (acc1[t][h * 2 + 0] + fb0) * sg0 + bb0;
                float v1 = (acc1[t][h * 2 + 1] + fb1) * sg1 + bb1;
                v0 = 0.5f * v0 * (1.f + erff(v0 * 0.70710678118654752f));
                v1 = 0.5f * v1 * (1.f + erff(v1 * 0.70710678118654752f));
                *(uint32_t*)(sm + j * GSTG128 + r * 128
                             + ((u ^ (r & 7)) << 4) + tg * 4) = pack2h(v0, v1);
            }
        }

        // load fc2w chunks into B-buffers
        #pragma unroll
        for (int jj = 0; jj < 3; jj++)
            #pragma unroll
            for (int i = 0; i < 3; i++) {
                const int idx = tid + i * 512;
                const int r = idx >> 3, p = idx & 7;
                cp16(sb + jj * GSTG128 + GA128 + r * 128 + ((p ^ (r & 7)) << 4),
                     g_fc2w + (size_t)r * MLPH + nt * 192 + jj * 64 + p * 8);
            }
        CP_COMMIT(); CP_WAIT0();
        __syncthreads();

        // fc2 partial: acc2 += hh_tile @ fc2w_tile^T
        #pragma unroll
        for (int jj = 0; jj < 3; jj++) {
            const uint32_t Ab = sb + (uint32_t)jj * GSTG128;
            const uint32_t Bb = Ab + GA128;
            #pragma unroll
            for (int ks = 0; ks < 4; ks++) {
                const int col = ks * 2 + chalf;
                uint32_t rA[2][4], rB[3][4];
                #pragma unroll
                for (int mi = 0; mi < 2; mi++) {
                    const int row = wm * 32 + mi * 16 + lrow;
                    ldm_x4(rA[mi], Ab + row * 128 + ((col ^ (row & 7)) << 4));
                }
                #pragma unroll
                for (int ni = 0; ni < 3; ni++) {
                    const int row = wn * 48 + ni * 16 + lrow;
                    ldm_x4(rB[ni], Bb + row * 128 + ((col ^ (row & 7)) << 4));
                }
                #pragma unroll
                for (int mi = 0; mi < 2; mi++)
                    #pragma unroll
                    for (int nj = 0; nj < 6; nj++)
                        mma16816(acc2[mi * 6 + nj], rA[mi],
                                 rB[nj >> 1][nj & 1], rB[nj >> 1][(nj & 1) + 2]);
            }
        }
        __syncthreads();
    }

    // epilogue: out = x + projo + (acc2 + fc2_b)
    float* shf = (float*)sm;   // [128][192] fp32
    #pragma unroll
    for (int t = 0; t < 12; t++) {
        const int mi = t / 6, nj = t % 6;
        const int cn = wn * 48 + nj * 8 + tg * 2;
        const float b0 = fc2_b[cn], b1 = fc2_b[cn + 1];
        #pragma unroll
        for (int h = 0; h < 2; h++) {
            const int r = wm * 32 + mi * 16 + g + h * 8;
            *(float2*)(shf + r * 192 + cn) =
                make_float2(acc2[t][h * 2 + 0] + b0, acc2[t][h * 2 + 1] + b1);
        }
    }
    __syncthreads();
    #pragma unroll
    for (int i = 0; i < 12; i++) {
        const int idx = tid + i * 512;        // 6144 float4
        const int r = idx / 48, q = idx - r * 48;
        const size_t o = (size_t)(m0 + r) * Cc + q * 4;
        float4 sv = *(const float4*)(shf + r * 192 + q * 4);
        float4 xv = *(const float4*)(x_shortcut + o);
        const uint2 pp = *(const uint2*)(g_po + o);
        const __half2 p0 = *(const __half2*)&pp.x;
        const __half2 p1 = *(const __half2*)&pp.y;
        *(float4*)(out + o) = make_float4(
            xv.x + __low2float(p0)  + sv.x,
            xv.y + __high2float(p0) + sv.y,
            xv.z + __low2float(p1)  + sv.z,
            xv.w + __high2float(p1) + sv.w);
    }
}

// ---------------- HMMA attention: 2 (window,head) pairs per CTA ----------
#define ATT_SQ 0
#define ATT_SK 5120
#define ATT_SV 10240
#define ATT_SB 15360
#define ATT_BYTES 16064   // per half, 16B-aligned

__global__ __launch_bounds__(256) void attn_kernel(
    const float* __restrict__ rpb, const float* __restrict__ gate)
{
    __shared__ __align__(16) char smboth[2 * ATT_BYTES];
    const int hp = threadIdx.x >> 7;          // which half-block
    char* sm = smboth + hp * ATT_BYTES;
    const uint32_t sb0 = smem_u32(sm);
    const int tid = threadIdx.x & 127;
    const int win  = blockIdx.x / 3;
    const int head = (blockIdx.x % 3) * 2 + hp;
    const size_t base = ((size_t)win * NHh + head) * (Nn * HD);

    for (int idx = tid; idx < 392; idx += 128) {
        const int a = idx / 196, e = idx - a * 196;
        const int r = e >> 2, p = e & 3;
        const __half* src = ((a == 0) ? g_q : g_k) + base + r * 32 + p * 8;
        *(uint4*)(sm + a * 5120 + r * ASTR + p * 16) = *(const uint4*)src;
    }
    for (int idx = tid; idx < 196; idx += 128) {
        const int r = idx >> 2, p = idx & 3;
        *(uint4*)(sm + ATT_SV + r * ASTR + p * 16) =
            *(const uint4*)(g_v + base + r * 32 + p * 8);
    }
    if (tid < 60) {
        const int r = 49 + (tid >> 2), p = tid & 3;
        *(uint4*)(sm + ATT_SV + r * ASTR + p * 16) = make_uint4(0, 0, 0, 0);
    }
    float* sbias = (float*)(sm + ATT_SB);
    for (int idx = tid; idx < 169; idx += 128) sbias[idx] = rpb[idx * NHh + head];
    __syncthreads();

    const int wid = tid >> 5, lane = tid & 31;
    const int g = lane >> 2, tg = lane & 3;
    const int lrow = lane & 15;
    const uint32_t koffh = (lane >> 4) << 4;

    float sacc[8][4];
    #pragma unroll
    for (int i = 0; i < 8; i++)
        #pragma unroll
        for (int j = 0; j < 4; j++) sacc[i][j] = 0.f;

    #pragma unroll
    for (int ks = 0; ks < 2; ks++) {
        const uint32_t koff = ks * 32 + koffh;
        uint32_t q[4], k[4][4];
        ldm_x4(q, sb0 + ATT_SQ + (wid * 16 + lrow) * ASTR + koff);
        #pragma unroll
        for (int nt = 0; nt < 4; nt++)
            ldm_x4(k[nt], sb0 + ATT_SK + (nt * 16 + lrow) * ASTR + koff);
        #pragma unroll
        for (int nj = 0; nj < 8; nj++)
            mma16816(sacc[nj], q, k[nj >> 1][nj & 1], k[nj >> 1][(nj & 1) + 2]);
    }

    const int w_ = win & 63;
    const bool er = ((w_ >> 3) == 7), ec = ((w_ & 7) == 7);
    int prr[2], pcc[2], gii[2];
    #pragma unroll
    for (int r = 0; r < 2; r++) {
        const int ii = min(wid * 16 + g + r * 8, 48);
        prr[r] = ii / 7; pcc[r] = ii - prr[r] * 7;
        gii[r] = (er ? ((prr[r] < 4) ? 1 : 2) : 0) * 3
               + (ec ? ((pcc[r] < 4) ? 1 : 2) : 0);
    }
    float mx[2] = {-1e30f, -1e30f};
    #pragma unroll
    for (int nj = 0; nj < 8; nj++)
        #pragma unroll
        for (int e = 0; e < 4; e++) {
            const int r = e >> 1;
            const int j = nj * 8 + tg * 2 + (e & 1);
            float s;
            if (j < Nn) {
                const int rj = j / 7, cj = j - rj * 7;
                const int gj = (er ? ((rj < 4) ? 1 : 2) : 0) * 3
                             + (ec ? ((cj < 4) ? 1 : 2) : 0);
                s = sacc[nj][e] + sbias[(prr[r] - rj + 6) * 13 + (pcc[r] - cj + 6)]
                    + ((gii[r] != gj) ? -100.f : 0.f);
            } else s = -1e30f;
            sacc[nj][e] = s;
            mx[r] = fmaxf(mx[r], s);
        }
    #pragma unroll
    for (int r = 0; r < 2; r++) {
        mx[r] = fmaxf(mx[r], __shfl_xor_sync(0xffffffffu, mx[r], 1));
        mx[r] = fmaxf(mx[r], __shfl_xor_sync(0xffffffffu, mx[r], 2));
    }
    float sum[2] = {0.f, 0.f};
    #pragma unroll
    for (int nj = 0; nj < 8; nj++)
        #pragma unroll
        for (int e = 0; e < 4; e++) {
            const float p = __expf(sacc[nj][e] - mx[e >> 1]);
            sacc[nj][e] = p;
            sum[e >> 1] += p;
        }
    #pragma unroll
    for (int r = 0; r < 2; r++) {
        sum[r] += __shfl_xor_sync(0xffffffffu, sum[r], 1);
        sum[r] += __shfl_xor_sync(0xffffffffu, sum[r], 2);
    }

    uint32_t Ph[8][2];
    #pragma unroll
    for (int nj = 0; nj < 8; nj++)
        #pragma unroll
        for (int r = 0; r < 2; r++)
            Ph[nj][r] = pack2h(sacc[nj][r * 2], sacc[nj][r * 2 + 1]);

    float oacc[4][4];
    #pragma unroll
    for (int i = 0; i < 4; i++)
        #pragma unroll
        for (int j = 0; j < 4; j++) oacc[i][j] = 0.f;

    #pragma unroll
    for (int s = 0; s < 4; s++) {
        uint32_t v0[4], v1[4];
        const uint32_t va = sb0 + ATT_SV + (s * 16 + (lane & 15)) * ASTR
                            + ((lane >> 4) << 4);
        ldm_x4t(v0, va);
        ldm_x4t(v1, va + 32);
        uint32_t aH[4] = {Ph[2*s][0], Ph[2*s][1], Ph[2*s+1][0], Ph[2*s+1][1]};
        mma16816(oacc[0], aH, v0[0], v0[1]);
        mma16816(oacc[1], aH, v0[2], v0[3]);
        mma16816(oacc[2], aH, v1[0], v1[1]);
        mma16816(oacc[3], aH, v1[2], v1[3]);
    }

    const float gval = 1.f / (1.f + expf(-gate[head]));
    #pragma unroll
    for (int r = 0; r < 2; r++) {
        const int i = wid * 16 + g + r * 8;
        if (i < Nn) {
            const float inv = gval / sum[r];
            const size_t rowb = ((size_t)win * Nn + i) * Cc + head * HD;
            #pragma unroll
            for (int nd = 0; nd < 4; nd++) {
                const size_t o = rowb + nd * 8 + tg * 2;
                *(uint32_t*)(g_o + o) = pack2h(oacc[nd][r * 2] * inv,
                                               oacc[nd][r * 2 + 1] * inv);
            }
        }
    }
}

// ---------------- LN1 + shift + window -> fp16 ----------------
__global__ void ln1_shift_window_kernel(const float* __restrict__ x,
                                        const float* __restrict__ g,
                                        const float* __restrict__ b)
{
    const int warp = threadIdx.x >> 5;
    const int lane = threadIdx.x & 31;
    const int t = blockIdx.x * 8 + warp;
    const int win = t / Nn;
    const int n   = t - win * Nn;
    const int bi  = win >> 6;
    const int w_  = win & 63;
    const int wr  = w_ >> 3, wc = w_ & 7;
    const int pr  = n / WS,  pc = n - (n / WS) * WS;
    int srow = wr * WS + pr + SS; if (srow >= Hh) srow -= Hh;
    int scol = wc * WS + pc + SS; if (scol >= Ww) scol -= Ww;
    const float* xp = x + ((size_t)bi * Ltok + srow * Ww + scol) * Cc;

    float v[6], s = 0.f, ss = 0.f;
    #pragma unroll
    for (int kq = 0; kq < 6; kq++) { v[kq] = xp[lane + 32 * kq]; s += v[kq]; ss += v[kq] * v[kq]; }
    #pragma unroll
    for (int off = 16; off > 0; off >>= 1) {
        s  += __shfl_xor_sync(0xffffffffu, s,  off);
        ss += __shfl_xor_sync(0xffffffffu, ss, off);
    }
    const float mean = s * (1.f / Cc);
    const float rstd = rsqrtf(ss * (1.f / Cc) - mean * mean + 1e-5f);
    #pragma unroll
    for (int kq = 0; kq < 6; kq++) {
        const int c = lane + 32 * kq;
        g_yw[(size_t)t * Cc + c] = __float2half((v[kq] - mean) * rstd * g[c] + b[c]);
    }
}

// ---------------- weight fp32 -> fp16 ----------------
__global__ void cvt_kernel(const float* __restrict__ s,
                           __half* __restrict__ h, int n)
{
    const int i = blockIdx.x * 256 + threadIdx.x;
    if (i < n) h[i] = __float2half(s[i]);
}

// ---------------- launch ----------------
extern "C" void kernel_launch(void* const* d_in, const int* in_sizes, int n_in,
                              void* d_out, int out_size)
{
    const float* x       = (const float*)d_in[0];
    const float* norm1_g = (const float*)d_in[1];
    const float* norm1_b = (const float*)d_in[2];
    const float* qkv_w   = (const float*)d_in[3];
    const float* qkv_b   = (const float*)d_in[4];
    const float* rpb     = (const float*)d_in[5];
    const float* gate    = (const float*)d_in[6];
    const float* proj_w  = (const float*)d_in[7];
    const float* proj_b  = (const float*)d_in[8];
    const float* norm2_g = (const float*)d_in[9];
    const float* norm2_b = (const float*)d_in[10];
    const float* fc1_w   = (const float*)d_in[11];
    const float* fc1_b   = (const float*)d_in[12];
    const float* bn_g    = (const float*)d_in[13];
    const float* bn_b    = (const float*)d_in[14];
    const float* fc2_w   = (const float*)d_in[15];
    const float* fc2_b   = (const float*)d_in[16];
    float* out = (float*)d_out;

    static bool attr_done = false;
    if (!attr_done) {
        cudaFuncSetAttribute(gemm_qkv_kernel,  cudaFuncAttributeMaxDynamicSharedMemorySize, SMEM_G128);
        cudaFuncSetAttribute(gemm_proj_kernel, cudaFuncAttributeMaxDynamicSharedMemorySize, SMEM_G128);
        cudaFuncSetAttribute(gemm_mlp_kernel,  cudaFuncAttributeMaxDynamicSharedMemorySize, SMEM_G128);
        attr_done = true;
    }

    __half *qw, *pw, *f1, *f2;
    cudaGetSymbolAddress((void**)&qw, g_qkvw);
    cudaGetSymbolAddress((void**)&pw, g_projw);
    cudaGetSymbolAddress((void**)&f1, g_fc1w);
    cudaGetSymbolAddress((void**)&f2, g_fc2w);

    cvt_kernel<<<(QKVN * Cc + 255) / 256, 256>>>(qkv_w, qw, QKVN * Cc);
    cvt_kernel<<<(Cc * Cc + 255) / 256, 256>>>(proj_w, pw, Cc * Cc);
    cvt_kernel<<<(MLPH * Cc + 255) / 256, 256>>>(fc1_w, f1, MLPH * Cc);
    cvt_kernel<<<(Cc * MLPH + 255) / 256, 256>>>(fc2_w, f2, Cc * MLPH);

    ln1_shift_window_kernel<<<Mrow / 8, 256>>>(x, norm1_g, norm1_b);
    gemm_qkv_kernel<<<Mrow / 128, 512, SMEM_G128>>>(qkv_b);
    attn_kernel<<<Bz * NW * 3, 256>>>(rpb, gate);
    gemm_proj_kernel<<<dim3(1, Mrow / 128), 512, SMEM_G128>>>(proj_b, x, norm2_g, norm2_b);
    gemm_mlp_kernel<<<dim3(1, Mrow / 128), 512, SMEM_G128>>>(fc1_b, bn_g, bn_b,
                                                             fc2_b, x, out);
}

// round 14
// speedup vs baseline: 1.0769x; 1.0769x over previous
#include <cuda_runtime.h>
#include <cuda_fp16.h>
#include <math.h>
#include <stdint.h>

// ---------------- problem constants ----------------
#define Bz    64
#define Hh    56
#define Ww    56
#define Cc    192
#define NHh   6
#define WS    7
#define SS    3
#define Nn    49
#define HD    32
#define NW    64
#define Ltok  3136
#define Mrow  200704      // B*L == 128*1568
#define MLPH  768
#define QKVN  576

// ---------------- scratch globals ----------------
__device__ __align__(16) __half g_yw[(size_t)Mrow * Cc];
__device__ __align__(16) __half g_q [(size_t)Mrow * Cc];
__device__ __align__(16) __half g_k [(size_t)Mrow * Cc];
__device__ __align__(16) __half g_v [(size_t)Mrow * Cc];
__device__ __align__(16) __half g_o [(size_t)Mrow * Cc];

// fp16 weights
__device__ __align__(16) __half g_qkvw[QKVN * Cc];
__device__ __align__(16) __half g_projw[Cc * Cc];
__device__ __align__(16) __half g_fc1w[MLPH * Cc];
__device__ __align__(16) __half g_fc2w[Cc * MLPH];

// ---------------- PTX helpers ----------------
__device__ __forceinline__ uint32_t smem_u32(const void* p) {
    uint32_t a;
    asm("{ .reg .u64 t; cvta.to.shared.u64 t, %1; cvt.u32.u64 %0, t; }"
        : "=r"(a) : "l"(p));
    return a;
}
__device__ __forceinline__ void cp16(uint32_t dst, const void* src) {
    asm volatile("cp.async.cg.shared.global [%0], [%1], 16;"
                 :: "r"(dst), "l"(src));
}
#define CP_COMMIT() asm volatile("cp.async.commit_group;" ::: "memory")
#define CP_WAIT1()  asm volatile("cp.async.wait_group 1;" ::: "memory")
#define CP_WAIT0()  asm volatile("cp.async.wait_group 0;" ::: "memory")

__device__ __forceinline__ void ldm_x4(uint32_t* r, uint32_t a) {
    asm volatile("ldmatrix.sync.aligned.m8n8.x4.shared.b16 {%0,%1,%2,%3}, [%4];"
        : "=r"(r[0]), "=r"(r[1]), "=r"(r[2]), "=r"(r[3]) : "r"(a));
}
__device__ __forceinline__ void ldm_x4t(uint32_t* r, uint32_t a) {
    asm volatile("ldmatrix.sync.aligned.m8n8.x4.trans.shared.b16 {%0,%1,%2,%3}, [%4];"
        : "=r"(r[0]), "=r"(r[1]), "=r"(r[2]), "=r"(r[3]) : "r"(a));
}
__device__ __forceinline__ void mma16816(float* d, const uint32_t* a,
                                         uint32_t b0, uint32_t b1) {
    asm volatile(
        "mma.sync.aligned.m16n8k16.row.col.f32.f16.f16.f32 "
        "{%0,%1,%2,%3}, {%4,%5,%6,%7}, {%8,%9}, {%0,%1,%2,%3};"
        : "+f"(d[0]), "+f"(d[1]), "+f"(d[2]), "+f"(d[3])
        : "r"(a[0]), "r"(a[1]), "r"(a[2]), "r"(a[3]), "r"(b0), "r"(b1));
}
__device__ __forceinline__ uint32_t pack2h(float v0, float v1) {
    __half2 h = __floats2half2_rn(v0, v1);
    return *(uint32_t*)&h;
}

// ---------------- GEMM geometry ----------------
#define GB_BYTES (192 * 128)
#define GA128    (128 * 128)
#define GSTG128  (GA128 + GB_BYTES)          // 40960
#define SMEM_G128 (3 * GSTG128)              // 122880
#define ASTR 80                               // attention smem row stride

// generic 3-stage pipelined mainloop (used by fused kernel's proj phase)
__device__ __forceinline__ void gemm_mma512(
    const __half* __restrict__ a, const __half* __restrict__ b,
    int K, int n0, int m0, float (&acc)[12][4])
{
    extern __shared__ char sm[];
    const uint32_t sb = smem_u32(sm);
    const int tid  = threadIdx.x;
    const int wid  = tid >> 5, lane = tid & 31;
    const int wm   = wid >> 2, wn = wid & 3;
    const int NCH  = K >> 6;

    #pragma unroll
    for (int i = 0; i < 12; i++)
        #pragma unroll
        for (int j = 0; j < 4; j++) acc[i][j] = 0.f;

    auto load_stage = [&](int stg, int c) {
        const __half* A = a + (size_t)m0 * K + c * 64;
        const __half* B = b + (size_t)n0 * K + c * 64;
        const uint32_t Ab = sb + (uint32_t)stg * GSTG128;
        const uint32_t Bb = Ab + GA128;
        #pragma unroll
        for (int i = 0; i < 2; i++) {
            const int idx = tid + i * 512;
            const int r = idx >> 3, p = idx & 7;
            cp16(Ab + r * 128 + ((p ^ (r & 7)) << 4), A + (size_t)r * K + p * 8);
        }
        #pragma unroll
        for (int i = 0; i < 3; i++) {
            const int idx = tid + i * 512;
            const int r = idx >> 3, p = idx & 7;
            cp16(Bb + r * 128 + ((p ^ (r & 7)) << 4), B + (size_t)r * K + p * 8);
        }
    };

    load_stage(0, 0); CP_COMMIT();
    load_stage(1, 1); CP_COMMIT();

    const int lrow  = lane & 15;
    const int chalf = lane >> 4;

    for (int c = 0; c < NCH; c++) {
        if (c < NCH - 1) { CP_WAIT1(); } else { CP_WAIT0(); }
        __syncthreads();
        const uint32_t Ab = sb + (uint32_t)(c % 3) * GSTG128;
        const uint32_t Bb = Ab + GA128;
        #pragma unroll
        for (int ks = 0; ks < 4; ks++) {
            const int col = ks * 2 + chalf;
            uint32_t rA[2][4], rB[3][4];
            #pragma unroll
            for (int mi = 0; mi < 2; mi++) {
                const int row = wm * 32 + mi * 16 + lrow;
                ldm_x4(rA[mi], Ab + row * 128 + ((col ^ (row & 7)) << 4));
            }
            #pragma unroll
            for (int ni = 0; ni < 3; ni++) {
                const int row = wn * 48 + ni * 16 + lrow;
                ldm_x4(rB[ni], Bb + row * 128 + ((col ^ (row & 7)) << 4));
            }
            #pragma unroll
            for (int mi = 0; mi < 2; mi++)
                #pragma unroll
                for (int nj = 0; nj < 6; nj++)
                    mma16816(acc[mi * 6 + nj], rA[mi],
                             rB[nj >> 1][nj & 1], rB[nj >> 1][(nj & 1) + 2]);
        }
        if (c + 2 < NCH) { load_stage((c + 2) % 3, c + 2); CP_COMMIT(); }
    }
    __syncthreads();   // smem buffers free
}

#define EPI_PROLOGUE()                                          \
    extern __shared__ char sm[];                                \
    const int tid = threadIdx.x;                                \
    const int wid = tid >> 5, lane = tid & 31;                  \
    const int wm = wid >> 2, wn = wid & 3;                      \
    const int g = lane >> 2, tg = lane & 3;

// ---------------- QKV GEMM: persistent-A, loops 3 parts -------------------
#define QB_OFF 49152
#define QB_STG 24576

__global__ __launch_bounds__(512) void gemm_qkv_kernel(const float* __restrict__ qkv_b)
{
    EPI_PROLOGUE();
    const uint32_t sb = smem_u32(sm);
    const int m0 = blockIdx.x * 128;
    const int lrow  = lane & 15;
    const int chalf = lane >> 4;

    #pragma unroll
    for (int i = 0; i < 6; i++) {
        const int idx = tid + i * 512;
        const int r = idx / 24, u = idx - r * 24;
        const int j = u >> 3, p = u & 7;
        cp16(sb + j * 16384 + r * 128 + ((p ^ (r & 7)) << 4),
             g_yw + (size_t)(m0 + r) * Cc + u * 8);
    }
    CP_COMMIT();

    auto load_B = [&](int stg, int part, int c) {
        const __half* B = g_qkvw + (size_t)part * 192 * Cc + c * 64;
        const uint32_t Bb = sb + QB_OFF + (uint32_t)stg * QB_STG;
        #pragma unroll
        for (int i = 0; i < 3; i++) {
            const int idx = tid + i * 512;
            const int r = idx >> 3, p = idx & 7;
            cp16(Bb + r * 128 + ((p ^ (r & 7)) << 4), B + (size_t)r * Cc + p * 8);
        }
    };

    for (int part = 0; part < 3; part++) {
        load_B(0, part, 0); CP_COMMIT();
        load_B(1, part, 1); CP_COMMIT();

        float acc[12][4];
        #pragma unroll
        for (int i = 0; i < 12; i++)
            #pragma unroll
            for (int j = 0; j < 4; j++) acc[i][j] = 0.f;

        #pragma unroll
        for (int c = 0; c < 3; c++) {
            if (c < 2) { CP_WAIT1(); } else { CP_WAIT0(); }
            __syncthreads();
            const uint32_t Ab = sb + (uint32_t)c * 16384;
            const uint32_t Bb = sb + QB_OFF + (uint32_t)c * QB_STG;
            #pragma unroll
            for (int ks = 0; ks < 4; ks++) {
                const int col = ks * 2 + chalf;
                uint32_t rA[2][4], rB[3][4];
                #pragma unroll
                for (int mi = 0; mi < 2; mi++) {
                    const int row = wm * 32 + mi * 16 + lrow;
                    ldm_x4(rA[mi], Ab + row * 128 + ((col ^ (row & 7)) << 4));
                }
                #pragma unroll
                for (int ni = 0; ni < 3; ni++) {
                    const int row = wn * 48 + ni * 16 + lrow;
                    ldm_x4(rB[ni], Bb + row * 128 + ((col ^ (row & 7)) << 4));
                }
                #pragma unroll
                for (int mi = 0; mi < 2; mi++)
                    #pragma unroll
                    for (int nj = 0; nj < 6; nj++)
                        mma16816(acc[mi * 6 + nj], rA[mi],
                                 rB[nj >> 1][nj & 1], rB[nj >> 1][(nj & 1) + 2]);
            }
            if (c == 0) { load_B(2, part, 2); CP_COMMIT(); }
        }
        __syncthreads();

        __half* dst = (part == 0) ? g_q : ((part == 1) ? g_k : g_v);
        const float sc = (part == 0) ? 0.17677669529663687f : 1.0f;
        __half* sh = (__half*)(sm + QB_OFF);
        #pragma unroll
        for (int t = 0; t < 12; t++) {
            const int mi = t / 6, nj = t % 6;
            const int c = wn * 48 + nj * 8 + tg * 2;
            const float b0 = qkv_b[part * 192 + c];
            const float b1 = qkv_b[part * 192 + c + 1];
            #pragma unroll
            for (int h = 0; h < 2; h++) {
                const int r = wm * 32 + mi * 16 + g + h * 8;
                *(uint32_t*)(sh + r * 192 + c) =
                    pack2h((acc[t][h * 2 + 0] + b0) * sc,
                           (acc[t][h * 2 + 1] + b1) * sc);
            }
        }
        __syncthreads();
        #pragma unroll
        for (int i = 0; i < 6; i++) {
            const int idx = tid + i * 512;
            const int r = idx / 24, s = idx - r * 24;
            const int head = s >> 2, d = (s & 3) * 8;
            const int m = m0 + r;
            const int win = m / Nn, n = m - win * Nn;
            const uint4 v = *(const uint4*)(sh + r * 192 + s * 8);
            *(uint4*)(dst + ((size_t)(win * NHh + head) * Nn + n) * HD + d) = v;
        }
        __syncthreads();
    }
}

// ---------------- MEGAFUSED: proj + LN2 + fc1 + BN/GELU + fc2 + residual --
// smem layout:
//   [0, 122880)        transient: proj staging / fc1-fc2 B staging + hh
//   [122880, 172032)   z fp16, 3 swizzled 64-col chunks (fc1 A operand)
//   [172032, 221184)   po fp16 [128][192]
//   [221184, 221696)   gi[128]: spatial row base (element offset)
#define Z_OFF   122880
#define PO_OFF  172032
#define GI_OFF  221184
#define HH_OFF  73728
#define SMEM_FUSE 221696

__global__ __launch_bounds__(512) void fused_block_kernel(
    const float* __restrict__ proj_b, const float* __restrict__ x_shortcut,
    const float* __restrict__ norm2_g, const float* __restrict__ norm2_b,
    const float* __restrict__ fc1_b, const float* __restrict__ bn_g,
    const float* __restrict__ bn_b,  const float* __restrict__ fc2_b,
    float* __restrict__ out)
{
    float acc[12][4];
    const int m0 = blockIdx.x * 128;
    gemm_mma512(g_o, g_projw, Cc, 0, m0, acc);     // proj mainloop
    EPI_PROLOGUE();
    const uint32_t sb = smem_u32(sm);
    const int lrow  = lane & 15;
    const int chalf = lane >> 4;

    // ---- stage proj+bias fp32 ----
    float* sh = (float*)sm;    // [128][192]
    #pragma unroll
    for (int t = 0; t < 12; t++) {
        const int mi = t / 6, nj = t % 6;
        const int cn = wn * 48 + nj * 8 + tg * 2;
        const float b0 = proj_b[cn], b1 = proj_b[cn + 1];
        #pragma unroll
        for (int h = 0; h < 2; h++) {
            const int r = wm * 32 + mi * 16 + g + h * 8;
            *(float2*)(sh + r * 192 + cn) =
                make_float2(acc[t][h * 2 + 0] + b0, acc[t][h * 2 + 1] + b1);
        }
    }
    __syncthreads();

    // ---- warp-per-row LN2: po->smem fp16, z->smem swizzled fp16 ----
    {
        float gg[6], bb[6];
        #pragma unroll
        for (int i = 0; i < 6; i++) {
            gg[i] = norm2_g[lane * 6 + i];
            bb[i] = norm2_b[lane * 6 + i];
        }
        __half* po_sm = (__half*)(sm + PO_OFF);
        int* gi = (int*)(sm + GI_OFF);
        for (int r = wid; r < 128; r += 16) {
            const int m = m0 + r;
            const int win = m / Nn, n = m - win * Nn;
            const int bi = win >> 6, w_ = win & 63;
            const int wr = w_ >> 3, wc = w_ & 7;
            const int pr = n / WS, pc = n - pr * WS;
            int ho = wr * WS + pr + SS; if (ho >= Hh) ho -= Hh;
            int wo = wc * WS + pc + SS; if (wo >= Ww) wo -= Ww;
            const int gidx = (bi * Ltok + ho * Ww + wo) * Cc;
            if (lane == 0) gi[r] = gidx;

            float v[6], po[6];
            const float* xr = x_shortcut + gidx + lane * 6;
            const float* sr = sh + r * 192 + lane * 6;
            float2 t0 = *(const float2*)(xr);
            float2 t1 = *(const float2*)(xr + 2);
            float2 t2 = *(const float2*)(xr + 4);
            po[0] = sr[0]; po[1] = sr[1]; po[2] = sr[2];
            po[3] = sr[3]; po[4] = sr[4]; po[5] = sr[5];
            v[0] = t0.x + po[0]; v[1] = t0.y + po[1];
            v[2] = t1.x + po[2]; v[3] = t1.y + po[3];
            v[4] = t2.x + po[4]; v[5] = t2.y + po[5];

            float s = 0.f, ss = 0.f;
            #pragma unroll
            for (int i = 0; i < 6; i++) { s += v[i]; ss += v[i] * v[i]; }
            #pragma unroll
            for (int off = 16; off > 0; off >>= 1) {
                s  += __shfl_xor_sync(0xffffffffu, s,  off);
                ss += __shfl_xor_sync(0xffffffffu, ss, off);
            }
            const float mean = s * (1.f / Cc);
            const float rstd = rsqrtf(ss * (1.f / Cc) - mean * mean + 1e-5f);

            __half* pw = po_sm + r * 192 + lane * 6;
            *(uint32_t*)(pw)     = pack2h(po[0], po[1]);
            *(uint32_t*)(pw + 2) = pack2h(po[2], po[3]);
            *(uint32_t*)(pw + 4) = pack2h(po[4], po[5]);

            #pragma unroll
            for (int i = 0; i < 6; i += 2) {
                const int c = lane * 6 + i;
                const int j = c >> 6, u = (c & 63) >> 3;
                *(uint32_t*)(sm + Z_OFF + j * 16384 + r * 128
                             + ((u ^ (r & 7)) << 4) + (c & 7) * 2) =
                    pack2h((v[i]-mean)*rstd*gg[i]+bb[i],
                           (v[i+1]-mean)*rstd*gg[i+1]+bb[i+1]);
            }
        }
    }
    __syncthreads();   // z/po/gi ready; transient region free

    // ---- MLP: 4 hidden sub-tiles, z resident, hh never leaves smem ----
    const float bnscale = 0.9999950000374997f;  // 1/sqrt(1+1e-5)
    float acc2[12][4];
    #pragma unroll
    for (int i = 0; i < 12; i++)
        #pragma unroll
        for (int j = 0; j < 4; j++) acc2[i][j] = 0.f;

    auto load_B1 = [&](int stg, int nt, int c) {   // fc1 weights
        const __half* B = g_fc1w + (size_t)(nt * 192) * Cc + c * 64;
        const uint32_t Bb = sb + (uint32_t)stg * QB_STG;
        #pragma unroll
        for (int i = 0; i < 3; i++) {
            const int idx = tid + i * 512;
            const int r = idx >> 3, p = idx & 7;
            cp16(Bb + r * 128 + ((p ^ (r & 7)) << 4), B + (size_t)r * Cc + p * 8);
        }
    };

    for (int nt = 0; nt < 4; nt++) {
        // fc1 mainloop: A = z (resident), B streamed
        load_B1(0, nt, 0); CP_COMMIT();
        load_B1(1, nt, 1); CP_COMMIT();
        float acc1[12][4];
        #pragma unroll
        for (int i = 0; i < 12; i++)
            #pragma unroll
            for (int j = 0; j < 4; j++) acc1[i][j] = 0.f;

        #pragma unroll
        for (int c = 0; c < 3; c++) {
            if (c < 2) { CP_WAIT1(); } else { CP_WAIT0(); }
            __syncthreads();
            const uint32_t Ab = sb + Z_OFF + (uint32_t)c * 16384;
            const uint32_t Bb = sb + (uint32_t)c * QB_STG;
            #pragma unroll
            for (int ks = 0; ks < 4; ks++) {
                const int col = ks * 2 + chalf;
                uint32_t rA[2][4], rB[3][4];
                #pragma unroll
                for (int mi = 0; mi < 2; mi++) {
                    const int row = wm * 32 + mi * 16 + lrow;
                    ldm_x4(rA[mi], Ab + row * 128 + ((col ^ (row & 7)) << 4));
                }
                #pragma unroll
                for (int ni = 0; ni < 3; ni++) {
                    const int row = wn * 48 + ni * 16 + lrow;
                    ldm_x4(rB[ni], Bb + row * 128 + ((col ^ (row & 7)) << 4));
                }
                #pragma unroll
                for (int mi = 0; mi < 2; mi++)
                    #pragma unroll
                    for (int nj = 0; nj < 6; nj++)
                        mma16816(acc1[mi * 6 + nj], rA[mi],
                                 rB[nj >> 1][nj & 1], rB[nj >> 1][(nj & 1) + 2]);
            }
            if (c == 0) { load_B1(2, nt, 2); CP_COMMIT(); }
        }

        // BN + GELU -> hh (swizzled, at HH_OFF; disjoint from B staging)
        #pragma unroll
        for (int t = 0; t < 12; t++) {
            const int mi = t / 6, nj = t % 6;
            const int c = wn * 48 + nj * 8 + tg * 2;
            const int cn = nt * 192 + c;
            const float fb0 = fc1_b[cn],  fb1 = fc1_b[cn + 1];
            const float sg0 = bnscale * bn_g[cn], sg1 = bnscale * bn_g[cn + 1];
            const float bb0 = bn_b[cn], bb1 = bn_b[cn + 1];
            const int j = c >> 6, u = (c & 63) >> 3;
            #pragma unroll
            for (int h = 0; h < 2; h++) {
                const int r = wm * 32 + mi * 16 + g + h * 8;
                float v0 = (acc1[t][h * 2 + 0] + fb0) * sg0 + bb0;
                float v1 = (acc1[t][h * 2 + 1] + fb1) * sg1 + bb1;
                v0 = 0.5f * v0 * (1.f + erff(v0 * 0.70710678118654752f));
                v1 = 0.5f * v1 * (1.f + erff(v1 * 0.70710678118654752f));
                *(uint32_t*)(sm + HH_OFF + j * 16384 + r * 128
                             + ((u ^ (r & 7)) << 4) + tg * 4) = pack2h(v0, v1);
            }
        }
        __syncthreads();   // hh visible; fc1 B staging free

        // load fc2w chunks into B staging [0, 73728)
        #pragma unroll
        for (int jj = 0; jj < 3; jj++)
            #pragma unroll
            for (int i = 0; i < 3; i++) {
                const int idx = tid + i * 512;
                const int r = idx >> 3, p = idx & 7;
                cp16(sb + jj * QB_STG + r * 128 + ((p ^ (r & 7)) << 4),
                     g_fc2w + (size_t)r * MLPH + nt * 192 + jj * 64 + p * 8);
            }
        CP_COMMIT(); CP_WAIT0();
        __syncthreads();

        // fc2 partial: acc2 += hh @ fc2w^T
        #pragma unroll
        for (int jj = 0; jj < 3; jj++) {
            const uint32_t Ab = sb + HH_OFF + (uint32_t)jj * 16384;
            const uint32_t Bb = sb + (uint32_t)jj * QB_STG;
            #pragma unroll
            for (int ks = 0; ks < 4; ks++) {
                const int col = ks * 2 + chalf;
                uint32_t rA[2][4], rB[3][4];
                #pragma unroll
                for (int mi = 0; mi < 2; mi++) {
                    const int row = wm * 32 + mi * 16 + lrow;
                    ldm_x4(rA[mi], Ab + row * 128 + ((col ^ (row & 7)) << 4));
                }
                #pragma unroll
                for (int ni = 0; ni < 3; ni++) {
                    const int row = wn * 48 + ni * 16 + lrow;
                    ldm_x4(rB[ni], Bb + row * 128 + ((col ^ (row & 7)) << 4));
                }
                #pragma unroll
                for (int mi = 0; mi < 2; mi++)
                    #pragma unroll
                    for (int nj = 0; nj < 6; nj++)
                        mma16816(acc2[mi * 6 + nj], rA[mi],
                                 rB[nj >> 1][nj & 1], rB[nj >> 1][(nj & 1) + 2]);
            }
        }
        __syncthreads();   // staging free for next nt
    }

    // ---- final epilogue: out = x + po + (acc2 + fc2_b), spatial rows ----
    float* shf = (float*)sm;   // [128][192] fp32
    #pragma unroll
    for (int t = 0; t < 12; t++) {
        const int mi = t / 6, nj = t % 6;
        const int cn = wn * 48 + nj * 8 + tg * 2;
        const float b0 = fc2_b[cn], b1 = fc2_b[cn + 1];
        #pragma unroll
        for (int h = 0; h < 2; h++) {
            const int r = wm * 32 + mi * 16 + g + h * 8;
            *(float2*)(shf + r * 192 + cn) =
                make_float2(acc2[t][h * 2 + 0] + b0, acc2[t][h * 2 + 1] + b1);
        }
    }
    __syncthreads();
    const int* gi = (const int*)(sm + GI_OFF);
    const __half* po_sm = (const __half*)(sm + PO_OFF);
    #pragma unroll
    for (int i = 0; i < 12; i++) {
        const int idx = tid + i * 512;        // 6144 float4
        const int r = idx / 48, q = idx - r * 48;
        const size_t o = (size_t)gi[r] + q * 4;
        float4 sv = *(const float4*)(shf + r * 192 + q * 4);
        float4 xv = *(const float4*)(x_shortcut + o);
        const uint2 pp = *(const uint2*)(po_sm + r * 192 + q * 4);
        const __half2 p0 = *(const __half2*)&pp.x;
        const __half2 p1 = *(const __half2*)&pp.y;
        *(float4*)(out + o) = make_float4(
            xv.x + __low2float(p0)  + sv.x,
            xv.y + __high2float(p0) + sv.y,
            xv.z + __low2float(p1)  + sv.z,
            xv.w + __high2float(p1) + sv.w);
    }
}

// ---------------- HMMA attention: 2 (window,head) pairs per CTA ----------
#define ATT_SQ 0
#define ATT_SK 5120
#define ATT_SV 10240
#define ATT_SB 15360
#define ATT_BYTES 16064

__global__ __launch_bounds__(256) void attn_kernel(
    const float* __restrict__ rpb, const float* __restrict__ gate)
{
    __shared__ __align__(16) char smboth[2 * ATT_BYTES];
    const int hp = threadIdx.x >> 7;
    char* sm = smboth + hp * ATT_BYTES;
    const uint32_t sb0 = smem_u32(sm);
    const int tid = threadIdx.x & 127;
    const int win  = blockIdx.x / 3;
    const int head = (blockIdx.x % 3) * 2 + hp;
    const size_t base = ((size_t)win * NHh + head) * (Nn * HD);

    for (int idx = tid; idx < 392; idx += 128) {
        const int a = idx / 196, e = idx - a * 196;
        const int r = e >> 2, p = e & 3;
        const __half* src = ((a == 0) ? g_q : g_k) + base + r * 32 + p * 8;
        *(uint4*)(sm + a * 5120 + r * ASTR + p * 16) = *(const uint4*)src;
    }
    for (int idx = tid; idx < 196; idx += 128) {
        const int r = idx >> 2, p = idx & 3;
        *(uint4*)(sm + ATT_SV + r * ASTR + p * 16) =
            *(const uint4*)(g_v + base + r * 32 + p * 8);
    }
    if (tid < 60) {
        const int r = 49 + (tid >> 2), p = tid & 3;
        *(uint4*)(sm + ATT_SV + r * ASTR + p * 16) = make_uint4(0, 0, 0, 0);
    }
    float* sbias = (float*)(sm + ATT_SB);
    for (int idx = tid; idx < 169; idx += 128) sbias[idx] = rpb[idx * NHh + head];
    __syncthreads();

    const int wid = tid >> 5, lane = tid & 31;
    const int g = lane >> 2, tg = lane & 3;
    const int lrow = lane & 15;
    const uint32_t koffh = (lane >> 4) << 4;

    float sacc[8][4];
    #pragma unroll
    for (int i = 0; i < 8; i++)
        #pragma unroll
        for (int j = 0; j < 4; j++) sacc[i][j] = 0.f;

    #pragma unroll
    for (int ks = 0; ks < 2; ks++) {
        const uint32_t koff = ks * 32 + koffh;
        uint32_t q[4], k[4][4];
        ldm_x4(q, sb0 + ATT_SQ + (wid * 16 + lrow) * ASTR + koff);
        #pragma unroll
        for (int nt = 0; nt < 4; nt++)
            ldm_x4(k[nt], sb0 + ATT_SK + (nt * 16 + lrow) * ASTR + koff);
        #pragma unroll
        for (int nj = 0; nj < 8; nj++)
            mma16816(sacc[nj], q, k[nj >> 1][nj & 1], k[nj >> 1][(nj & 1) + 2]);
    }

    const int w_ = win & 63;
    const bool er = ((w_ >> 3) == 7), ec = ((w_ & 7) == 7);
    int prr[2], pcc[2], gii[2];
    #pragma unroll
    for (int r = 0; r < 2; r++) {
        const int ii = min(wid * 16 + g + r * 8, 48);
        prr[r] = ii / 7; pcc[r] = ii - prr[r] * 7;
        gii[r] = (er ? ((prr[r] < 4) ? 1 : 2) : 0) * 3
               + (ec ? ((pcc[r] < 4) ? 1 : 2) : 0);
    }
    float mx[2] = {-1e30f, -1e30f};
    #pragma unroll
    for (int nj = 0; nj < 8; nj++)
        #pragma unroll
        for (int e = 0; e < 4; e++) {
            const int r = e >> 1;
            const int j = nj * 8 + tg * 2 + (e & 1);
            float s;
            if (j < Nn) {
                const int rj = j / 7, cj = j - rj * 7;
                const int gj = (er ? ((rj < 4) ? 1 : 2) : 0) * 3
                             + (ec ? ((cj < 4) ? 1 : 2) : 0);
                s = sacc[nj][e] + sbias[(prr[r] - rj + 6) * 13 + (pcc[r] - cj + 6)]
                    + ((gii[r] != gj) ? -100.f : 0.f);
            } else s = -1e30f;
            sacc[nj][e] = s;
            mx[r] = fmaxf(mx[r], s);
        }
    #pragma unroll
    for (int r = 0; r < 2; r++) {
        mx[r] = fmaxf(mx[r], __shfl_xor_sync(0xffffffffu, mx[r], 1));
        mx[r] = fmaxf(mx[r], __shfl_xor_sync(0xffffffffu, mx[r], 2));
    }
    float sum[2] = {0.f, 0.f};
    #pragma unroll
    for (int nj = 0; nj < 8; nj++)
        #pragma unroll
        for (int e = 0; e < 4; e++) {
            const float p = __expf(sacc[nj][e] - mx[e >> 1]);
            sacc[nj][e] = p;
            sum[e >> 1] += p;
        }
    #pragma unroll
    for (int r = 0; r < 2; r++) {
        sum[r] += __shfl_xor_sync(0xffffffffu, sum[r], 1);
        sum[r] += __shfl_xor_sync(0xffffffffu, sum[r], 2);
    }

    uint32_t Ph[8][2];
    #pragma unroll
    for (int nj = 0; nj < 8; nj++)
        #pragma unroll
        for (int r = 0; r < 2; r++)
            Ph[nj][r] = pack2h(sacc[nj][r * 2], sacc[nj][r * 2 + 1]);

    float oacc[4][4];
    #pragma unroll
    for (int i = 0; i < 4; i++)
        #pragma unroll
        for (int j = 0; j < 4; j++) oacc[i][j] = 0.f;

    #pragma unroll
    for (int s = 0; s < 4; s++) {
        uint32_t v0[4], v1[4];
        const uint32_t va = sb0 + ATT_SV + (s * 16 + (lane & 15)) * ASTR
                            + ((lane >> 4) << 4);
        ldm_x4t(v0, va);
        ldm_x4t(v1, va + 32);
        uint32_t aH[4] = {Ph[2*s][0], Ph[2*s][1], Ph[2*s+1][0], Ph[2*s+1][1]};
        mma16816(oacc[0], aH, v0[0], v0[1]);
        mma16816(oacc[1], aH, v0[2], v0[3]);
        mma16816(oacc[2], aH, v1[0], v1[1]);
        mma16816(oacc[3], aH, v1[2], v1[3]);
    }

    const float gval = 1.f / (1.f + expf(-gate[head]));
    #pragma unroll
    for (int r = 0; r < 2; r++) {
        const int i = wid * 16 + g + r * 8;
        if (i < Nn) {
            const float inv = gval / sum[r];
            const size_t rowb = ((size_t)win * Nn + i) * Cc + head * HD;
            #pragma unroll
            for (int nd = 0; nd < 4; nd++) {
                const size_t o = rowb + nd * 8 + tg * 2;
                *(uint32_t*)(g_o + o) = pack2h(oacc[nd][r * 2] * inv,
                                               oacc[nd][r * 2 + 1] * inv);
            }
        }
    }
}

// ---------------- LN1 + shift + window -> fp16 ----------------
__global__ void ln1_shift_window_kernel(const float* __restrict__ x,
                                        const float* __restrict__ g,
                                        const float* __restrict__ b)
{
    const int warp = threadIdx.x >> 5;
    const int lane = threadIdx.x & 31;
    const int t = blockIdx.x * 8 + warp;
    const int win = t / Nn;
    const int n   = t - win * Nn;
    const int bi  = win >> 6;
    const int w_  = win & 63;
    const int wr  = w_ >> 3, wc = w_ & 7;
    const int pr  = n / WS,  pc = n - (n / WS) * WS;
    int srow = wr * WS + pr + SS; if (srow >= Hh) srow -= Hh;
    int scol = wc * WS + pc + SS; if (scol >= Ww) scol -= Ww;
    const float* xp = x + ((size_t)bi * Ltok + srow * Ww + scol) * Cc;

    float v[6], s = 0.f, ss = 0.f;
    #pragma unroll
    for (int kq = 0; kq < 6; kq++) { v[kq] = xp[lane + 32 * kq]; s += v[kq]; ss += v[kq] * v[kq]; }
    #pragma unroll
    for (int off = 16; off > 0; off >>= 1) {
        s  += __shfl_xor_sync(0xffffffffu, s,  off);
        ss += __shfl_xor_sync(0xffffffffu, ss, off);
    }
    const float mean = s * (1.f / Cc);
    const float rstd = rsqrtf(ss * (1.f / Cc) - mean * mean + 1e-5f);
    #pragma unroll
    for (int kq = 0; kq < 6; kq++) {
        const int c = lane + 32 * kq;
        g_yw[(size_t)t * Cc + c] = __float2half((v[kq] - mean) * rstd * g[c] + b[c]);
    }
}

// ---------------- weight fp32 -> fp16 ----------------
__global__ void cvt_kernel(const float* __restrict__ s,
                           __half* __restrict__ h, int n)
{
    const int i = blockIdx.x * 256 + threadIdx.x;
    if (i < n) h[i] = __float2half(s[i]);
}

// ---------------- launch ----------------
extern "C" void kernel_launch(void* const* d_in, const int* in_sizes, int n_in,
                              void* d_out, int out_size)
{
    const float* x       = (const float*)d_in[0];
    const float* norm1_g = (const float*)d_in[1];
    const float* norm1_b = (const float*)d_in[2];
    const float* qkv_w   = (const float*)d_in[3];
    const float* qkv_b   = (const float*)d_in[4];
    const float* rpb     = (const float*)d_in[5];
    const float* gate    = (const float*)d_in[6];
    const float* proj_w  = (const float*)d_in[7];
    const float* proj_b  = (const float*)d_in[8];
    const float* norm2_g = (const float*)d_in[9];
    const float* norm2_b = (const float*)d_in[10];
    const float* fc1_w   = (const float*)d_in[11];
    const float* fc1_b   = (const float*)d_in[12];
    const float* bn_g    = (const float*)d_in[13];
    const float* bn_b    = (const float*)d_in[14];
    const float* fc2_w   = (const float*)d_in[15];
    const float* fc2_b   = (const float*)d_in[16];
    float* out = (float*)d_out;

    static bool attr_done = false;
    if (!attr_done) {
        cudaFuncSetAttribute(gemm_qkv_kernel,   cudaFuncAttributeMaxDynamicSharedMemorySize, SMEM_G128);
        cudaFuncSetAttribute(fused_block_kernel, cudaFuncAttributeMaxDynamicSharedMemorySize, SMEM_FUSE);
        attr_done = true;
    }

    __half *qw, *pw, *f1, *f2;
    cudaGetSymbolAddress((void**)&qw, g_qkvw);
    cudaGetSymbolAddress((void**)&pw, g_projw);
    cudaGetSymbolAddress((void**)&f1, g_fc1w);
    cudaGetSymbolAddress((void**)&f2, g_fc2w);

    cvt_kernel<<<(QKVN * Cc + 255) / 256, 256>>>(qkv_w, qw, QKVN * Cc);
    cvt_kernel<<<(Cc * Cc + 255) / 256, 256>>>(proj_w, pw, Cc * Cc);
    cvt_kernel<<<(MLPH * Cc + 255) / 256, 256>>>(fc1_w, f1, MLPH * Cc);
    cvt_kernel<<<(Cc * MLPH + 255) / 256, 256>>>(fc2_w, f2, Cc * MLPH);

    ln1_shift_window_kernel<<<Mrow / 8, 256>>>(x, norm1_g, norm1_b);
    gemm_qkv_kernel<<<Mrow / 128, 512, SMEM_G128>>>(qkv_b);
    attn_kernel<<<Bz * NW * 3, 256>>>(rpb, gate);
    fused_block_kernel<<<Mrow / 128, 512, SMEM_FUSE>>>(
        proj_b, x, norm2_g, norm2_b, fc1_b, bn_g, bn_b, fc2_b, out);
}